// round 12
// baseline (speedup 1.0000x reference)
#include <cuda_runtime.h>
#include <cuda_fp16.h>

#define NMAX_NODES 50000
#define NMAX_EDGES 800000

// Scratch (device globals; no allocation allowed)
__device__ __half g_zh[NMAX_NODES * 128];
__device__ float  g_ssrc[NMAX_NODES];
__device__ float  g_sdst[NMAX_NODES];
__device__ float  g_se[NMAX_EDGES];
__device__ int    g_deg[NMAX_NODES];
__device__ int    g_start[NMAX_NODES];
__device__ int    g_cursor[NMAX_NODES];
__device__ int    g_blocksum[256];
__device__ int    g_bar;              // grid barrier counter (reset by k_edge_place)
__device__ uint2  g_pe[NMAX_EDGES];   // packed (src, ssrc[src]+s_e), dst-sorted

__device__ __forceinline__ unsigned smem_u32(const void* p) {
    unsigned a;
    asm("{ .reg .u64 t; cvta.to.shared.u64 t, %1; cvt.u32.u64 %0, t; }"
        : "=r"(a) : "l"(p));
    return a;
}

__device__ __forceinline__ void ldsm_x4(unsigned& r0, unsigned& r1, unsigned& r2,
                                        unsigned& r3, unsigned addr) {
    asm volatile("ldmatrix.sync.aligned.m8n8.x4.shared.b16 {%0,%1,%2,%3}, [%4];"
                 : "=r"(r0), "=r"(r1), "=r"(r2), "=r"(r3) : "r"(addr));
}
__device__ __forceinline__ void ldsm_x2(unsigned& r0, unsigned& r1, unsigned addr) {
    asm volatile("ldmatrix.sync.aligned.m8n8.x2.shared.b16 {%0,%1}, [%2];"
                 : "=r"(r0), "=r"(r1) : "r"(addr));
}
__device__ __forceinline__ void mma16816(float* c, const unsigned* a, const unsigned* b) {
    asm volatile(
        "mma.sync.aligned.m16n8k16.row.col.f32.f16.f16.f32 "
        "{%0,%1,%2,%3}, {%4,%5,%6,%7}, {%8,%9}, {%0,%1,%2,%3};"
        : "+f"(c[0]), "+f"(c[1]), "+f"(c[2]), "+f"(c[3])
        : "r"(a[0]), "r"(a[1]), "r"(a[2]), "r"(a[3]), "r"(b[0]), "r"(b[1]));
}

__device__ __forceinline__ unsigned pack_h2(float a, float b) {
    __half2 h = __floats2half2_rn(a, b);
    return *reinterpret_cast<unsigned*>(&h);
}

// ---------------------------------------------------------------------------
// K1: z = nfeats @ W_fc^T via HMMA, fp32 inputs converted inline.
// Fused epilogue: fp16 z, s_src/s_dst dots, AND deg zeroing.
// ---------------------------------------------------------------------------
#define ASTR 136                 // padded row stride in halfs
#define GEMMH_SMEM (2 * 128 * ASTR * 2 + 288 * 4)

__global__ __launch_bounds__(256) void k_gemm_h(const float* __restrict__ nf,
                                                const float* __restrict__ W,
                                                const float* __restrict__ Wa,
                                                int n_nodes) {
    extern __shared__ __half hsm[];
    __half* sA = hsm;             // [128][ASTR]
    __half* sB = hsm + 128 * ASTR;
    float* sWa = reinterpret_cast<float*>(hsm + 2 * 128 * ASTR);  // [288]
    int tid = threadIdx.x;
    int rowBase = blockIdx.x * 128;

    if (tid < 144) {
        ((float2*)sWa)[tid] = ((const float2*)Wa)[tid];  // 288 floats
    }
#pragma unroll
    for (int c = tid; c < 2048; c += 256) {
        int row = c >> 4;
        int col16 = c & 15;                 // 8-half chunk
        int r = rowBase + row;
        uint4 hv = make_uint4(0u, 0u, 0u, 0u);
        if (r < n_nodes) {
            float4 v0 = ((const float4*)nf)[(size_t)r * 32 + col16 * 2];
            float4 v1 = ((const float4*)nf)[(size_t)r * 32 + col16 * 2 + 1];
            hv.x = pack_h2(v0.x, v0.y);
            hv.y = pack_h2(v0.z, v0.w);
            hv.z = pack_h2(v1.x, v1.y);
            hv.w = pack_h2(v1.z, v1.w);
        }
        *reinterpret_cast<uint4*>(sA + row * ASTR + col16 * 8) = hv;
        float4 w0 = ((const float4*)W)[row * 32 + col16 * 2];
        float4 w1 = ((const float4*)W)[row * 32 + col16 * 2 + 1];
        uint4 wv;
        wv.x = pack_h2(w0.x, w0.y);
        wv.y = pack_h2(w0.z, w0.w);
        wv.z = pack_h2(w1.x, w1.y);
        wv.w = pack_h2(w1.z, w1.w);
        *reinterpret_cast<uint4*>(sB + row * ASTR + col16 * 8) = wv;
    }
    __syncthreads();

    int warp = tid >> 5;
    int lane = tid & 31;
    int m0 = warp * 16;

    float acc[16][4];
#pragma unroll
    for (int nt = 0; nt < 16; nt++)
#pragma unroll
        for (int j = 0; j < 4; j++) acc[nt][j] = 0.f;

    unsigned aBase = smem_u32(sA) + ((m0 + (lane & 15)) * ASTR + ((lane >> 4) << 3)) * 2;
    unsigned bBase = smem_u32(sB) + ((lane & 7) * ASTR + (((lane >> 3) & 1) << 3)) * 2;

#pragma unroll
    for (int ks = 0; ks < 8; ks++) {
        unsigned a[4];
        ldsm_x4(a[0], a[1], a[2], a[3], aBase + ks * 32);
#pragma unroll
        for (int nt = 0; nt < 16; nt++) {
            unsigned b[2];
            ldsm_x2(b[0], b[1], bBase + (nt * 8 * ASTR) * 2 + ks * 32);
            mma16816(acc[nt], a, b);
        }
    }

    // Epilogue: z (fp16) + fused s_src/s_dst partial dots + deg zeroing
    int gr = lane >> 2;
    int colq = (lane & 3) * 2;
    int r0 = rowBase + m0 + gr;
    int r1 = r0 + 8;
    float v1a = 0.f, v2a = 0.f, v1b = 0.f, v2b = 0.f;
#pragma unroll
    for (int nt = 0; nt < 16; nt++) {
        int col = nt * 8 + colq;
        float as0 = sWa[col], as1 = sWa[col + 1];
        float ad0 = sWa[160 + col], ad1 = sWa[161 + col];
        v1a += acc[nt][0] * as0 + acc[nt][1] * as1;
        v2a += acc[nt][0] * ad0 + acc[nt][1] * ad1;
        v1b += acc[nt][2] * as0 + acc[nt][3] * as1;
        v2b += acc[nt][2] * ad0 + acc[nt][3] * ad1;
        if (r0 < n_nodes) {
            unsigned h = pack_h2(acc[nt][0], acc[nt][1]);
            *reinterpret_cast<unsigned*>(g_zh + (size_t)r0 * 128 + col) = h;
        }
        if (r1 < n_nodes) {
            unsigned h = pack_h2(acc[nt][2], acc[nt][3]);
            *reinterpret_cast<unsigned*>(g_zh + (size_t)r1 * 128 + col) = h;
        }
    }
#pragma unroll
    for (int o = 1; o <= 2; o <<= 1) {
        v1a += __shfl_xor_sync(0xffffffffu, v1a, o);
        v2a += __shfl_xor_sync(0xffffffffu, v2a, o);
        v1b += __shfl_xor_sync(0xffffffffu, v1b, o);
        v2b += __shfl_xor_sync(0xffffffffu, v2b, o);
    }
    if ((lane & 3) == 0) {
        if (r0 < n_nodes) { g_ssrc[r0] = v1a; g_sdst[r0] = v2a; g_deg[r0] = 0; }
        if (r1 < n_nodes) { g_ssrc[r1] = v1b; g_sdst[r1] = v2b; g_deg[r1] = 0; }
    }
}

// ---------------------------------------------------------------------------
// K2: coalesced s_e = efeats·a_e + deg histogram. Warp = 32 edges (MLP=8).
// ---------------------------------------------------------------------------
__global__ __launch_bounds__(256) void k_se_hist(const float* __restrict__ ef,
                                                 const float* __restrict__ Wa,
                                                 const int* __restrict__ dst,
                                                 int n_edges) {
    __shared__ float sa[32];
    if (threadIdx.x < 32) sa[threadIdx.x] = Wa[128 + threadIdx.x];  // a_e
    __syncthreads();
    int warp = (blockIdx.x * blockDim.x + threadIdx.x) >> 5;
    int lane = threadIdx.x & 31;
    int sub = lane >> 3;
    int g = lane & 7;
    int e0 = warp * 32 + sub;

    float4 x[8];
#pragma unroll
    for (int u = 0; u < 8; u++) {
        int e = e0 + u * 4;
        x[u] = (e < n_edges) ? __ldg((const float4*)ef + (size_t)e * 8 + g)
                             : make_float4(0.f, 0.f, 0.f, 0.f);
    }
    float c0 = sa[g * 4], c1 = sa[g * 4 + 1], c2 = sa[g * 4 + 2], c3 = sa[g * 4 + 3];
    float v[8];
#pragma unroll
    for (int u = 0; u < 8; u++)
        v[u] = x[u].x * c0 + x[u].y * c1 + x[u].z * c2 + x[u].w * c3;
#pragma unroll
    for (int u = 0; u < 8; u++) {
        v[u] += __shfl_xor_sync(0xffffffffu, v[u], 4);
        v[u] += __shfl_xor_sync(0xffffffffu, v[u], 2);
        v[u] += __shfl_xor_sync(0xffffffffu, v[u], 1);
    }
    if (g == 0) {
#pragma unroll
        for (int u = 0; u < 8; u++) {
            int e = e0 + u * 4;
            if (e < n_edges) {
                g_se[e] = v[u];
                atomicAdd(&g_deg[dst[e]], 1);
            }
        }
    }
}

// ---------------------------------------------------------------------------
// K3: SINGLE-LAUNCH exclusive scan of deg -> start/cursor.
// 196 blocks (trivially co-resident) + device grid barrier.
// g_bar is reset to 0 by k_edge_place (stream-ordered before next replay).
// ---------------------------------------------------------------------------
__global__ __launch_bounds__(256) void k_scan(int n, int nb) {
    __shared__ int s[256];
    int t = threadIdx.x;
    int i = blockIdx.x * 256 + t;
    int v = (i < n) ? g_deg[i] : 0;
    s[t] = v;
    __syncthreads();
#pragma unroll
    for (int off = 1; off < 256; off <<= 1) {
        int x = (t >= off) ? s[t - off] : 0;
        __syncthreads();
        s[t] += x;
        __syncthreads();
    }
    int local_ex = s[t] - v;            // exclusive within block
    if (t == 255) g_blocksum[blockIdx.x] = s[255];

    // grid barrier
    __threadfence();
    __syncthreads();
    if (t == 0) {
        atomicAdd(&g_bar, 1);
        while (*((volatile int*)&g_bar) < nb) { }
    }
    __syncthreads();

    // phase 2: every block scans the blocksums (read L2-coherently)
    int bv = (t < nb) ? __ldcg(&g_blocksum[t]) : 0;
    s[t] = bv;
    __syncthreads();
#pragma unroll
    for (int off = 1; off < 256; off <<= 1) {
        int x = (t >= off) ? s[t - off] : 0;
        __syncthreads();
        s[t] += x;
        __syncthreads();
    }
    int offset = (blockIdx.x == 0) ? 0 : s[blockIdx.x - 1];
    if (i < n) {
        int st = local_ex + offset;
        g_start[i] = st;
        g_cursor[i] = st;
    }
}

// ---------------------------------------------------------------------------
// K4: per edge: t = ssrc[src] + s_e; place packed (src, t) into dst-sorted
//     position. 4 edges per thread, vector front loads (4 indep chains).
//     Also resets the scan barrier counter for the next replay.
// ---------------------------------------------------------------------------
__global__ __launch_bounds__(256) void k_edge_place(const int* __restrict__ src,
                                                    const int* __restrict__ dst,
                                                    int n_edges) {
    if (blockIdx.x == 0 && threadIdx.x == 0) g_bar = 0;  // reset for next replay
    int base = (blockIdx.x * blockDim.x + threadIdx.x) * 4;
    if (base + 3 < n_edges) {
        int4 s4 = *reinterpret_cast<const int4*>(src + base);
        int4 d4 = *reinterpret_cast<const int4*>(dst + base);
        float4 se4 = *reinterpret_cast<const float4*>(g_se + base);
        float t0 = __ldg(&g_ssrc[s4.x]) + se4.x;
        float t1 = __ldg(&g_ssrc[s4.y]) + se4.y;
        float t2 = __ldg(&g_ssrc[s4.z]) + se4.z;
        float t3 = __ldg(&g_ssrc[s4.w]) + se4.w;
        int p0 = atomicAdd(&g_cursor[d4.x], 1);
        int p1 = atomicAdd(&g_cursor[d4.y], 1);
        int p2 = atomicAdd(&g_cursor[d4.z], 1);
        int p3 = atomicAdd(&g_cursor[d4.w], 1);
        g_pe[p0] = make_uint2((unsigned)s4.x, __float_as_uint(t0));
        g_pe[p1] = make_uint2((unsigned)s4.y, __float_as_uint(t1));
        g_pe[p2] = make_uint2((unsigned)s4.z, __float_as_uint(t2));
        g_pe[p3] = make_uint2((unsigned)s4.w, __float_as_uint(t3));
    } else {
        for (int e = base; e < n_edges; e++) {
            int s = src[e];
            int d = dst[e];
            float t = __ldg(&g_ssrc[s]) + g_se[e];
            int pos = atomicAdd(&g_cursor[d], 1);
            g_pe[pos] = make_uint2((unsigned)s, __float_as_uint(t));
        }
    }
}

// ---------------------------------------------------------------------------
// K5: HALF-WARP per dst node (16 lanes, uint4 gathers).
//     w_e = exp(leaky(t_e + sdst[d])); h[d] = (sum w_e*zh[src_e]) / sum w_e.
// ---------------------------------------------------------------------------
__global__ __launch_bounds__(256) void k_agg(float* __restrict__ out, int n_nodes) {
    int gw = (blockIdx.x * blockDim.x + threadIdx.x) >> 5;
    int lane = threadIdx.x & 31;
    int half = lane >> 4;
    int hl = lane & 15;
    int d = gw * 2 + half;
    if (d >= n_nodes) return;
    unsigned mask = half ? 0xFFFF0000u : 0x0000FFFFu;
    int lbase = half << 4;

    int start = g_start[d];
    int deg = g_deg[d];
    float sdst_d = g_sdst[d];
    float acc[8];
#pragma unroll
    for (int u = 0; u < 8; u++) acc[u] = 0.f;
    float wsum = 0.f;

    for (int i = 0; i < deg; i += 16) {
        int s = 0;
        float wv = 0.f;
        if (i + hl < deg) {
            uint2 p = g_pe[start + i + hl];
            s = (int)p.x;
            float ev = __uint_as_float(p.y) + sdst_d;
            ev = (ev > 0.f) ? ev : 0.01f * ev;
            wv = __expf(ev);
        }
        wsum += wv;
        int cnt = min(16, deg - i);
        int j = 0;
#define ACC_EDGE(hz, wj)                                                       \
        {                                                                      \
            float2 f0 = __half22float2(*reinterpret_cast<__half2*>(&hz.x));    \
            float2 f1 = __half22float2(*reinterpret_cast<__half2*>(&hz.y));    \
            float2 f2 = __half22float2(*reinterpret_cast<__half2*>(&hz.z));    \
            float2 f3 = __half22float2(*reinterpret_cast<__half2*>(&hz.w));    \
            acc[0] += (wj) * f0.x; acc[1] += (wj) * f0.y;                      \
            acc[2] += (wj) * f1.x; acc[3] += (wj) * f1.y;                      \
            acc[4] += (wj) * f2.x; acc[5] += (wj) * f2.y;                      \
            acc[6] += (wj) * f3.x; acc[7] += (wj) * f3.y;                      \
        }
        for (; j + 4 <= cnt; j += 4) {
            int s0 = __shfl_sync(mask, s, lbase + j);
            int s1 = __shfl_sync(mask, s, lbase + j + 1);
            int s2 = __shfl_sync(mask, s, lbase + j + 2);
            int s3 = __shfl_sync(mask, s, lbase + j + 3);
            float w0 = __shfl_sync(mask, wv, lbase + j);
            float w1 = __shfl_sync(mask, wv, lbase + j + 1);
            float w2 = __shfl_sync(mask, wv, lbase + j + 2);
            float w3 = __shfl_sync(mask, wv, lbase + j + 3);
            uint4 h0 = *reinterpret_cast<const uint4*>(g_zh + (size_t)s0 * 128 + hl * 8);
            uint4 h1 = *reinterpret_cast<const uint4*>(g_zh + (size_t)s1 * 128 + hl * 8);
            uint4 h2 = *reinterpret_cast<const uint4*>(g_zh + (size_t)s2 * 128 + hl * 8);
            uint4 h3 = *reinterpret_cast<const uint4*>(g_zh + (size_t)s3 * 128 + hl * 8);
            ACC_EDGE(h0, w0)
            ACC_EDGE(h1, w1)
            ACC_EDGE(h2, w2)
            ACC_EDGE(h3, w3)
        }
        for (; j < cnt; j++) {
            int sj = __shfl_sync(mask, s, lbase + j);
            float wj = __shfl_sync(mask, wv, lbase + j);
            uint4 hz = *reinterpret_cast<const uint4*>(g_zh + (size_t)sj * 128 + hl * 8);
            ACC_EDGE(hz, wj)
        }
#undef ACC_EDGE
    }
#pragma unroll
    for (int o = 1; o <= 8; o <<= 1)
        wsum += __shfl_xor_sync(mask, wsum, o);
    float dinv = (wsum > 0.f) ? 1.0f / wsum : 0.f;
    float4* op = (float4*)(out + (size_t)d * 128 + hl * 8);
    op[0] = make_float4(acc[0] * dinv, acc[1] * dinv, acc[2] * dinv, acc[3] * dinv);
    op[1] = make_float4(acc[4] * dinv, acc[5] * dinv, acc[6] * dinv, acc[7] * dinv);
}

// ---------------------------------------------------------------------------
extern "C" void kernel_launch(void* const* d_in, const int* in_sizes, int n_in,
                              void* d_out, int out_size) {
    const float* nf  = (const float*)d_in[0];
    const float* ef  = (const float*)d_in[1];
    const float* Wfc = (const float*)d_in[2];
    const float* Wa  = (const float*)d_in[3];
    const int*   src = (const int*)d_in[4];
    const int*   dst = (const int*)d_in[5];
    float* out = (float*)d_out;

    int n_nodes = in_sizes[0] / 128;
    int n_edges = in_sizes[4];
    int nscan = (n_nodes + 255) / 256;  // 196 (<= 256, co-resident)

    cudaFuncSetAttribute(k_gemm_h, cudaFuncAttributeMaxDynamicSharedMemorySize, GEMMH_SMEM);

    k_gemm_h<<<(n_nodes + 127) / 128, 256, GEMMH_SMEM>>>(nf, Wfc, Wa, n_nodes);
    k_se_hist<<<(n_edges + 255) / 256, 256>>>(ef, Wa, dst, n_edges);
    k_scan<<<nscan, 256>>>(n_nodes, nscan);
    k_edge_place<<<(n_edges + 1023) / 1024, 256>>>(src, dst, n_edges);
    k_agg<<<(n_nodes + 15) / 16, 256>>>(out, n_nodes);
}

// round 13
// speedup vs baseline: 1.0222x; 1.0222x over previous
#include <cuda_runtime.h>
#include <cuda_fp16.h>

#define NMAX_NODES 50000
#define NMAX_EDGES 800000

// Scratch (device globals; no allocation allowed)
__device__ __half g_zh[NMAX_NODES * 128];
__device__ float  g_ssrc[NMAX_NODES];
__device__ float  g_sdst[NMAX_NODES];
__device__ float  g_se[NMAX_EDGES];
__device__ int    g_deg[NMAX_NODES];
__device__ int    g_start[NMAX_NODES];
__device__ int    g_cursor[NMAX_NODES];
__device__ int    g_blocksum[256];
__device__ int    g_bar;              // grid barrier counter (reset by k_edge_place)
__device__ uint2  g_pe[NMAX_EDGES];   // packed (src, ssrc[src]+s_e), dst-sorted

__device__ __forceinline__ unsigned smem_u32(const void* p) {
    unsigned a;
    asm("{ .reg .u64 t; cvta.to.shared.u64 t, %1; cvt.u32.u64 %0, t; }"
        : "=r"(a) : "l"(p));
    return a;
}

__device__ __forceinline__ void ldsm_x4(unsigned& r0, unsigned& r1, unsigned& r2,
                                        unsigned& r3, unsigned addr) {
    asm volatile("ldmatrix.sync.aligned.m8n8.x4.shared.b16 {%0,%1,%2,%3}, [%4];"
                 : "=r"(r0), "=r"(r1), "=r"(r2), "=r"(r3) : "r"(addr));
}
__device__ __forceinline__ void ldsm_x2(unsigned& r0, unsigned& r1, unsigned addr) {
    asm volatile("ldmatrix.sync.aligned.m8n8.x2.shared.b16 {%0,%1}, [%2];"
                 : "=r"(r0), "=r"(r1) : "r"(addr));
}
__device__ __forceinline__ void mma16816(float* c, const unsigned* a, const unsigned* b) {
    asm volatile(
        "mma.sync.aligned.m16n8k16.row.col.f32.f16.f16.f32 "
        "{%0,%1,%2,%3}, {%4,%5,%6,%7}, {%8,%9}, {%0,%1,%2,%3};"
        : "+f"(c[0]), "+f"(c[1]), "+f"(c[2]), "+f"(c[3])
        : "r"(a[0]), "r"(a[1]), "r"(a[2]), "r"(a[3]), "r"(b[0]), "r"(b[1]));
}

__device__ __forceinline__ unsigned pack_h2(float a, float b) {
    __half2 h = __floats2half2_rn(a, b);
    return *reinterpret_cast<unsigned*>(&h);
}

// ---------------------------------------------------------------------------
// K1: z = nfeats @ W_fc^T via HMMA, fp32 inputs converted inline.
// Fused epilogue: fp16 z, s_src/s_dst dots, AND deg zeroing.
// ---------------------------------------------------------------------------
#define ASTR 136                 // padded row stride in halfs
#define GEMMH_SMEM (2 * 128 * ASTR * 2 + 288 * 4)

__global__ __launch_bounds__(256) void k_gemm_h(const float* __restrict__ nf,
                                                const float* __restrict__ W,
                                                const float* __restrict__ Wa,
                                                int n_nodes) {
    extern __shared__ __half hsm[];
    __half* sA = hsm;             // [128][ASTR]
    __half* sB = hsm + 128 * ASTR;
    float* sWa = reinterpret_cast<float*>(hsm + 2 * 128 * ASTR);  // [288]
    int tid = threadIdx.x;
    int rowBase = blockIdx.x * 128;

    if (tid < 144) {
        ((float2*)sWa)[tid] = ((const float2*)Wa)[tid];  // 288 floats
    }
#pragma unroll
    for (int c = tid; c < 2048; c += 256) {
        int row = c >> 4;
        int col16 = c & 15;                 // 8-half chunk
        int r = rowBase + row;
        uint4 hv = make_uint4(0u, 0u, 0u, 0u);
        if (r < n_nodes) {
            float4 v0 = ((const float4*)nf)[(size_t)r * 32 + col16 * 2];
            float4 v1 = ((const float4*)nf)[(size_t)r * 32 + col16 * 2 + 1];
            hv.x = pack_h2(v0.x, v0.y);
            hv.y = pack_h2(v0.z, v0.w);
            hv.z = pack_h2(v1.x, v1.y);
            hv.w = pack_h2(v1.z, v1.w);
        }
        *reinterpret_cast<uint4*>(sA + row * ASTR + col16 * 8) = hv;
        float4 w0 = ((const float4*)W)[row * 32 + col16 * 2];
        float4 w1 = ((const float4*)W)[row * 32 + col16 * 2 + 1];
        uint4 wv;
        wv.x = pack_h2(w0.x, w0.y);
        wv.y = pack_h2(w0.z, w0.w);
        wv.z = pack_h2(w1.x, w1.y);
        wv.w = pack_h2(w1.z, w1.w);
        *reinterpret_cast<uint4*>(sB + row * ASTR + col16 * 8) = wv;
    }
    __syncthreads();

    int warp = tid >> 5;
    int lane = tid & 31;
    int m0 = warp * 16;

    float acc[16][4];
#pragma unroll
    for (int nt = 0; nt < 16; nt++)
#pragma unroll
        for (int j = 0; j < 4; j++) acc[nt][j] = 0.f;

    unsigned aBase = smem_u32(sA) + ((m0 + (lane & 15)) * ASTR + ((lane >> 4) << 3)) * 2;
    unsigned bBase = smem_u32(sB) + ((lane & 7) * ASTR + (((lane >> 3) & 1) << 3)) * 2;

#pragma unroll
    for (int ks = 0; ks < 8; ks++) {
        unsigned a[4];
        ldsm_x4(a[0], a[1], a[2], a[3], aBase + ks * 32);
#pragma unroll
        for (int nt = 0; nt < 16; nt++) {
            unsigned b[2];
            ldsm_x2(b[0], b[1], bBase + (nt * 8 * ASTR) * 2 + ks * 32);
            mma16816(acc[nt], a, b);
        }
    }

    // Epilogue: z (fp16) + fused s_src/s_dst partial dots + deg zeroing
    int gr = lane >> 2;
    int colq = (lane & 3) * 2;
    int r0 = rowBase + m0 + gr;
    int r1 = r0 + 8;
    float v1a = 0.f, v2a = 0.f, v1b = 0.f, v2b = 0.f;
#pragma unroll
    for (int nt = 0; nt < 16; nt++) {
        int col = nt * 8 + colq;
        float as0 = sWa[col], as1 = sWa[col + 1];
        float ad0 = sWa[160 + col], ad1 = sWa[161 + col];
        v1a += acc[nt][0] * as0 + acc[nt][1] * as1;
        v2a += acc[nt][0] * ad0 + acc[nt][1] * ad1;
        v1b += acc[nt][2] * as0 + acc[nt][3] * as1;
        v2b += acc[nt][2] * ad0 + acc[nt][3] * ad1;
        if (r0 < n_nodes) {
            unsigned h = pack_h2(acc[nt][0], acc[nt][1]);
            *reinterpret_cast<unsigned*>(g_zh + (size_t)r0 * 128 + col) = h;
        }
        if (r1 < n_nodes) {
            unsigned h = pack_h2(acc[nt][2], acc[nt][3]);
            *reinterpret_cast<unsigned*>(g_zh + (size_t)r1 * 128 + col) = h;
        }
    }
#pragma unroll
    for (int o = 1; o <= 2; o <<= 1) {
        v1a += __shfl_xor_sync(0xffffffffu, v1a, o);
        v2a += __shfl_xor_sync(0xffffffffu, v2a, o);
        v1b += __shfl_xor_sync(0xffffffffu, v1b, o);
        v2b += __shfl_xor_sync(0xffffffffu, v2b, o);
    }
    if ((lane & 3) == 0) {
        if (r0 < n_nodes) { g_ssrc[r0] = v1a; g_sdst[r0] = v2a; g_deg[r0] = 0; }
        if (r1 < n_nodes) { g_ssrc[r1] = v1b; g_sdst[r1] = v2b; g_deg[r1] = 0; }
    }
}

// ---------------------------------------------------------------------------
// K2: coalesced s_e = efeats·a_e + deg histogram. Warp = 32 edges (MLP=8).
// ---------------------------------------------------------------------------
__global__ __launch_bounds__(256) void k_se_hist(const float* __restrict__ ef,
                                                 const float* __restrict__ Wa,
                                                 const int* __restrict__ dst,
                                                 int n_edges) {
    __shared__ float sa[32];
    if (threadIdx.x < 32) sa[threadIdx.x] = Wa[128 + threadIdx.x];  // a_e
    __syncthreads();
    int warp = (blockIdx.x * blockDim.x + threadIdx.x) >> 5;
    int lane = threadIdx.x & 31;
    int sub = lane >> 3;
    int g = lane & 7;
    int e0 = warp * 32 + sub;

    float4 x[8];
#pragma unroll
    for (int u = 0; u < 8; u++) {
        int e = e0 + u * 4;
        x[u] = (e < n_edges) ? __ldg((const float4*)ef + (size_t)e * 8 + g)
                             : make_float4(0.f, 0.f, 0.f, 0.f);
    }
    float c0 = sa[g * 4], c1 = sa[g * 4 + 1], c2 = sa[g * 4 + 2], c3 = sa[g * 4 + 3];
    float v[8];
#pragma unroll
    for (int u = 0; u < 8; u++)
        v[u] = x[u].x * c0 + x[u].y * c1 + x[u].z * c2 + x[u].w * c3;
#pragma unroll
    for (int u = 0; u < 8; u++) {
        v[u] += __shfl_xor_sync(0xffffffffu, v[u], 4);
        v[u] += __shfl_xor_sync(0xffffffffu, v[u], 2);
        v[u] += __shfl_xor_sync(0xffffffffu, v[u], 1);
    }
    if (g == 0) {
#pragma unroll
        for (int u = 0; u < 8; u++) {
            int e = e0 + u * 4;
            if (e < n_edges) {
                g_se[e] = v[u];
                atomicAdd(&g_deg[dst[e]], 1);
            }
        }
    }
}

// ---------------------------------------------------------------------------
// K3: SINGLE-LAUNCH exclusive scan of deg -> start/cursor.
// 196 blocks (trivially co-resident) + device grid barrier.
// g_bar is reset to 0 by k_edge_place (stream-ordered before next replay).
// ---------------------------------------------------------------------------
__global__ __launch_bounds__(256) void k_scan(int n, int nb) {
    __shared__ int s[256];
    int t = threadIdx.x;
    int i = blockIdx.x * 256 + t;
    int v = (i < n) ? g_deg[i] : 0;
    s[t] = v;
    __syncthreads();
#pragma unroll
    for (int off = 1; off < 256; off <<= 1) {
        int x = (t >= off) ? s[t - off] : 0;
        __syncthreads();
        s[t] += x;
        __syncthreads();
    }
    int local_ex = s[t] - v;            // exclusive within block
    if (t == 255) g_blocksum[blockIdx.x] = s[255];

    // grid barrier
    __threadfence();
    __syncthreads();
    if (t == 0) {
        atomicAdd(&g_bar, 1);
        while (*((volatile int*)&g_bar) < nb) { }
    }
    __syncthreads();

    // phase 2: every block scans the blocksums (read L2-coherently)
    int bv = (t < nb) ? __ldcg(&g_blocksum[t]) : 0;
    s[t] = bv;
    __syncthreads();
#pragma unroll
    for (int off = 1; off < 256; off <<= 1) {
        int x = (t >= off) ? s[t - off] : 0;
        __syncthreads();
        s[t] += x;
        __syncthreads();
    }
    int offset = (blockIdx.x == 0) ? 0 : s[blockIdx.x - 1];
    if (i < n) {
        int st = local_ex + offset;
        g_start[i] = st;
        g_cursor[i] = st;
    }
}

// ---------------------------------------------------------------------------
// K4: per edge: t = ssrc[src] + s_e; place packed (src, t) into dst-sorted
//     position. 2 edges per thread (best-measured ILP/TLP balance).
//     Also resets the scan barrier counter for the next replay.
// ---------------------------------------------------------------------------
__global__ __launch_bounds__(256) void k_edge_place(const int* __restrict__ src,
                                                    const int* __restrict__ dst,
                                                    int n_edges) {
    if (blockIdx.x == 0 && threadIdx.x == 0) g_bar = 0;  // reset for next replay
    int base = (blockIdx.x * blockDim.x + threadIdx.x) * 2;
    if (base >= n_edges) return;
    int e0 = base;
    int e1 = base + 1;
    bool ok1 = (e1 < n_edges);

    int s0 = src[e0];
    int d0 = dst[e0];
    float se0 = g_se[e0];
    int s1 = ok1 ? src[e1] : 0;
    int d1 = ok1 ? dst[e1] : 0;
    float se1 = ok1 ? g_se[e1] : 0.f;

    float t0 = __ldg(&g_ssrc[s0]) + se0;
    float t1 = ok1 ? (__ldg(&g_ssrc[s1]) + se1) : 0.f;

    int pos0 = atomicAdd(&g_cursor[d0], 1);
    g_pe[pos0] = make_uint2((unsigned)s0, __float_as_uint(t0));
    if (ok1) {
        int pos1 = atomicAdd(&g_cursor[d1], 1);
        g_pe[pos1] = make_uint2((unsigned)s1, __float_as_uint(t1));
    }
}

// ---------------------------------------------------------------------------
// K5: HALF-WARP per dst node (16 lanes, uint4 gathers).
//     w_e = exp(leaky(t_e + sdst[d])); h[d] = (sum w_e*zh[src_e]) / sum w_e.
// ---------------------------------------------------------------------------
__global__ __launch_bounds__(256) void k_agg(float* __restrict__ out, int n_nodes) {
    int gw = (blockIdx.x * blockDim.x + threadIdx.x) >> 5;
    int lane = threadIdx.x & 31;
    int half = lane >> 4;
    int hl = lane & 15;
    int d = gw * 2 + half;
    if (d >= n_nodes) return;
    unsigned mask = half ? 0xFFFF0000u : 0x0000FFFFu;
    int lbase = half << 4;

    int start = g_start[d];
    int deg = g_deg[d];
    float sdst_d = g_sdst[d];
    float acc[8];
#pragma unroll
    for (int u = 0; u < 8; u++) acc[u] = 0.f;
    float wsum = 0.f;

    for (int i = 0; i < deg; i += 16) {
        int s = 0;
        float wv = 0.f;
        if (i + hl < deg) {
            uint2 p = g_pe[start + i + hl];
            s = (int)p.x;
            float ev = __uint_as_float(p.y) + sdst_d;
            ev = (ev > 0.f) ? ev : 0.01f * ev;
            wv = __expf(ev);
        }
        wsum += wv;
        int cnt = min(16, deg - i);
        int j = 0;
#define ACC_EDGE(hz, wj)                                                       \
        {                                                                      \
            float2 f0 = __half22float2(*reinterpret_cast<__half2*>(&hz.x));    \
            float2 f1 = __half22float2(*reinterpret_cast<__half2*>(&hz.y));    \
            float2 f2 = __half22float2(*reinterpret_cast<__half2*>(&hz.z));    \
            float2 f3 = __half22float2(*reinterpret_cast<__half2*>(&hz.w));    \
            acc[0] += (wj) * f0.x; acc[1] += (wj) * f0.y;                      \
            acc[2] += (wj) * f1.x; acc[3] += (wj) * f1.y;                      \
            acc[4] += (wj) * f2.x; acc[5] += (wj) * f2.y;                      \
            acc[6] += (wj) * f3.x; acc[7] += (wj) * f3.y;                      \
        }
        for (; j + 4 <= cnt; j += 4) {
            int s0 = __shfl_sync(mask, s, lbase + j);
            int s1 = __shfl_sync(mask, s, lbase + j + 1);
            int s2 = __shfl_sync(mask, s, lbase + j + 2);
            int s3 = __shfl_sync(mask, s, lbase + j + 3);
            float w0 = __shfl_sync(mask, wv, lbase + j);
            float w1 = __shfl_sync(mask, wv, lbase + j + 1);
            float w2 = __shfl_sync(mask, wv, lbase + j + 2);
            float w3 = __shfl_sync(mask, wv, lbase + j + 3);
            uint4 h0 = *reinterpret_cast<const uint4*>(g_zh + (size_t)s0 * 128 + hl * 8);
            uint4 h1 = *reinterpret_cast<const uint4*>(g_zh + (size_t)s1 * 128 + hl * 8);
            uint4 h2 = *reinterpret_cast<const uint4*>(g_zh + (size_t)s2 * 128 + hl * 8);
            uint4 h3 = *reinterpret_cast<const uint4*>(g_zh + (size_t)s3 * 128 + hl * 8);
            ACC_EDGE(h0, w0)
            ACC_EDGE(h1, w1)
            ACC_EDGE(h2, w2)
            ACC_EDGE(h3, w3)
        }
        for (; j < cnt; j++) {
            int sj = __shfl_sync(mask, s, lbase + j);
            float wj = __shfl_sync(mask, wv, lbase + j);
            uint4 hz = *reinterpret_cast<const uint4*>(g_zh + (size_t)sj * 128 + hl * 8);
            ACC_EDGE(hz, wj)
        }
#undef ACC_EDGE
    }
#pragma unroll
    for (int o = 1; o <= 8; o <<= 1)
        wsum += __shfl_xor_sync(mask, wsum, o);
    float dinv = (wsum > 0.f) ? 1.0f / wsum : 0.f;
    float4* op = (float4*)(out + (size_t)d * 128 + hl * 8);
    op[0] = make_float4(acc[0] * dinv, acc[1] * dinv, acc[2] * dinv, acc[3] * dinv);
    op[1] = make_float4(acc[4] * dinv, acc[5] * dinv, acc[6] * dinv, acc[7] * dinv);
}

// ---------------------------------------------------------------------------
extern "C" void kernel_launch(void* const* d_in, const int* in_sizes, int n_in,
                              void* d_out, int out_size) {
    const float* nf  = (const float*)d_in[0];
    const float* ef  = (const float*)d_in[1];
    const float* Wfc = (const float*)d_in[2];
    const float* Wa  = (const float*)d_in[3];
    const int*   src = (const int*)d_in[4];
    const int*   dst = (const int*)d_in[5];
    float* out = (float*)d_out;

    int n_nodes = in_sizes[0] / 128;
    int n_edges = in_sizes[4];
    int nscan = (n_nodes + 255) / 256;  // 196 (<= 256, co-resident)

    cudaFuncSetAttribute(k_gemm_h, cudaFuncAttributeMaxDynamicSharedMemorySize, GEMMH_SMEM);

    k_gemm_h<<<(n_nodes + 127) / 128, 256, GEMMH_SMEM>>>(nf, Wfc, Wa, n_nodes);
    k_se_hist<<<(n_edges + 255) / 256, 256>>>(ef, Wa, dst, n_edges);
    k_scan<<<nscan, 256>>>(n_nodes, nscan);
    k_edge_place<<<(n_edges + 511) / 512, 256>>>(src, dst, n_edges);
    k_agg<<<(n_nodes + 15) / 16, 256>>>(out, n_nodes);
}

// round 14
// speedup vs baseline: 1.0258x; 1.0035x over previous
#include <cuda_runtime.h>
#include <cuda_fp16.h>

#define NMAX_NODES 50000
#define NMAX_EDGES 800000

// Scratch (device globals; no allocation allowed)
__device__ __half g_zh[NMAX_NODES * 128];
__device__ float  g_ssrc[NMAX_NODES];
__device__ float  g_sdst[NMAX_NODES];
__device__ float  g_t[NMAX_EDGES];     // ssrc[src[e]] + s_e
__device__ int    g_rank[NMAX_EDGES];  // rank within dst segment (from histogram)
__device__ int    g_deg[NMAX_NODES];
__device__ int    g_start[NMAX_NODES];
__device__ int    g_blocksum[256];
__device__ int    g_bar;               // grid barrier counter (reset by k_edge_place)
__device__ uint2  g_pe[NMAX_EDGES];    // packed (src, t), dst-sorted

__device__ __forceinline__ unsigned smem_u32(const void* p) {
    unsigned a;
    asm("{ .reg .u64 t; cvta.to.shared.u64 t, %1; cvt.u32.u64 %0, t; }"
        : "=r"(a) : "l"(p));
    return a;
}

__device__ __forceinline__ void ldsm_x4(unsigned& r0, unsigned& r1, unsigned& r2,
                                        unsigned& r3, unsigned addr) {
    asm volatile("ldmatrix.sync.aligned.m8n8.x4.shared.b16 {%0,%1,%2,%3}, [%4];"
                 : "=r"(r0), "=r"(r1), "=r"(r2), "=r"(r3) : "r"(addr));
}
__device__ __forceinline__ void ldsm_x2(unsigned& r0, unsigned& r1, unsigned addr) {
    asm volatile("ldmatrix.sync.aligned.m8n8.x2.shared.b16 {%0,%1}, [%2];"
                 : "=r"(r0), "=r"(r1) : "r"(addr));
}
__device__ __forceinline__ void mma16816(float* c, const unsigned* a, const unsigned* b) {
    asm volatile(
        "mma.sync.aligned.m16n8k16.row.col.f32.f16.f16.f32 "
        "{%0,%1,%2,%3}, {%4,%5,%6,%7}, {%8,%9}, {%0,%1,%2,%3};"
        : "+f"(c[0]), "+f"(c[1]), "+f"(c[2]), "+f"(c[3])
        : "r"(a[0]), "r"(a[1]), "r"(a[2]), "r"(a[3]), "r"(b[0]), "r"(b[1]));
}

__device__ __forceinline__ unsigned pack_h2(float a, float b) {
    __half2 h = __floats2half2_rn(a, b);
    return *reinterpret_cast<unsigned*>(&h);
}

// ---------------------------------------------------------------------------
// K1: z = nfeats @ W_fc^T via HMMA, fp32 inputs converted inline.
// Fused epilogue: fp16 z, s_src/s_dst dots, AND deg zeroing.
// ---------------------------------------------------------------------------
#define ASTR 136                 // padded row stride in halfs
#define GEMMH_SMEM (2 * 128 * ASTR * 2 + 288 * 4)

__global__ __launch_bounds__(256) void k_gemm_h(const float* __restrict__ nf,
                                                const float* __restrict__ W,
                                                const float* __restrict__ Wa,
                                                int n_nodes) {
    extern __shared__ __half hsm[];
    __half* sA = hsm;             // [128][ASTR]
    __half* sB = hsm + 128 * ASTR;
    float* sWa = reinterpret_cast<float*>(hsm + 2 * 128 * ASTR);  // [288]
    int tid = threadIdx.x;
    int rowBase = blockIdx.x * 128;

    if (tid < 144) {
        ((float2*)sWa)[tid] = ((const float2*)Wa)[tid];  // 288 floats
    }
#pragma unroll
    for (int c = tid; c < 2048; c += 256) {
        int row = c >> 4;
        int col16 = c & 15;                 // 8-half chunk
        int r = rowBase + row;
        uint4 hv = make_uint4(0u, 0u, 0u, 0u);
        if (r < n_nodes) {
            float4 v0 = ((const float4*)nf)[(size_t)r * 32 + col16 * 2];
            float4 v1 = ((const float4*)nf)[(size_t)r * 32 + col16 * 2 + 1];
            hv.x = pack_h2(v0.x, v0.y);
            hv.y = pack_h2(v0.z, v0.w);
            hv.z = pack_h2(v1.x, v1.y);
            hv.w = pack_h2(v1.z, v1.w);
        }
        *reinterpret_cast<uint4*>(sA + row * ASTR + col16 * 8) = hv;
        float4 w0 = ((const float4*)W)[row * 32 + col16 * 2];
        float4 w1 = ((const float4*)W)[row * 32 + col16 * 2 + 1];
        uint4 wv;
        wv.x = pack_h2(w0.x, w0.y);
        wv.y = pack_h2(w0.z, w0.w);
        wv.z = pack_h2(w1.x, w1.y);
        wv.w = pack_h2(w1.z, w1.w);
        *reinterpret_cast<uint4*>(sB + row * ASTR + col16 * 8) = wv;
    }
    __syncthreads();

    int warp = tid >> 5;
    int lane = tid & 31;
    int m0 = warp * 16;

    float acc[16][4];
#pragma unroll
    for (int nt = 0; nt < 16; nt++)
#pragma unroll
        for (int j = 0; j < 4; j++) acc[nt][j] = 0.f;

    unsigned aBase = smem_u32(sA) + ((m0 + (lane & 15)) * ASTR + ((lane >> 4) << 3)) * 2;
    unsigned bBase = smem_u32(sB) + ((lane & 7) * ASTR + (((lane >> 3) & 1) << 3)) * 2;

#pragma unroll
    for (int ks = 0; ks < 8; ks++) {
        unsigned a[4];
        ldsm_x4(a[0], a[1], a[2], a[3], aBase + ks * 32);
#pragma unroll
        for (int nt = 0; nt < 16; nt++) {
            unsigned b[2];
            ldsm_x2(b[0], b[1], bBase + (nt * 8 * ASTR) * 2 + ks * 32);
            mma16816(acc[nt], a, b);
        }
    }

    // Epilogue: z (fp16) + fused s_src/s_dst partial dots + deg zeroing
    int gr = lane >> 2;
    int colq = (lane & 3) * 2;
    int r0 = rowBase + m0 + gr;
    int r1 = r0 + 8;
    float v1a = 0.f, v2a = 0.f, v1b = 0.f, v2b = 0.f;
#pragma unroll
    for (int nt = 0; nt < 16; nt++) {
        int col = nt * 8 + colq;
        float as0 = sWa[col], as1 = sWa[col + 1];
        float ad0 = sWa[160 + col], ad1 = sWa[161 + col];
        v1a += acc[nt][0] * as0 + acc[nt][1] * as1;
        v2a += acc[nt][0] * ad0 + acc[nt][1] * ad1;
        v1b += acc[nt][2] * as0 + acc[nt][3] * as1;
        v2b += acc[nt][2] * ad0 + acc[nt][3] * ad1;
        if (r0 < n_nodes) {
            unsigned h = pack_h2(acc[nt][0], acc[nt][1]);
            *reinterpret_cast<unsigned*>(g_zh + (size_t)r0 * 128 + col) = h;
        }
        if (r1 < n_nodes) {
            unsigned h = pack_h2(acc[nt][2], acc[nt][3]);
            *reinterpret_cast<unsigned*>(g_zh + (size_t)r1 * 128 + col) = h;
        }
    }
#pragma unroll
    for (int o = 1; o <= 2; o <<= 1) {
        v1a += __shfl_xor_sync(0xffffffffu, v1a, o);
        v2a += __shfl_xor_sync(0xffffffffu, v2a, o);
        v1b += __shfl_xor_sync(0xffffffffu, v1b, o);
        v2b += __shfl_xor_sync(0xffffffffu, v2b, o);
    }
    if ((lane & 3) == 0) {
        if (r0 < n_nodes) { g_ssrc[r0] = v1a; g_sdst[r0] = v2a; g_deg[r0] = 0; }
        if (r1 < n_nodes) { g_ssrc[r1] = v1b; g_sdst[r1] = v2b; g_deg[r1] = 0; }
    }
}

// ---------------------------------------------------------------------------
// K2: coalesced s_e = efeats·a_e (MLP=8) + FULL-WIDTH fused tail:
// reduced dots redistributed via smem so each of the 32 lanes owns ONE edge,
// then t = ssrc[src]+s_e (coalesced + 1 gather) and rank = histogram atomic.
// ---------------------------------------------------------------------------
__global__ __launch_bounds__(256) void k_se_hist(const float* __restrict__ ef,
                                                 const float* __restrict__ Wa,
                                                 const int* __restrict__ src,
                                                 const int* __restrict__ dst,
                                                 int n_edges) {
    __shared__ float sa[32];
    __shared__ float sv[8][32];          // per-warp redistributed dots
    if (threadIdx.x < 32) sa[threadIdx.x] = Wa[128 + threadIdx.x];  // a_e
    __syncthreads();
    int wid = threadIdx.x >> 5;
    int warp = (blockIdx.x * blockDim.x + threadIdx.x) >> 5;
    int lane = threadIdx.x & 31;
    int sub = lane >> 3;
    int g = lane & 7;
    int e0 = warp * 32 + sub;

    float4 x[8];
#pragma unroll
    for (int u = 0; u < 8; u++) {
        int e = e0 + u * 4;
        x[u] = (e < n_edges) ? __ldg((const float4*)ef + (size_t)e * 8 + g)
                             : make_float4(0.f, 0.f, 0.f, 0.f);
    }
    float c0 = sa[g * 4], c1 = sa[g * 4 + 1], c2 = sa[g * 4 + 2], c3 = sa[g * 4 + 3];
    float v[8];
#pragma unroll
    for (int u = 0; u < 8; u++)
        v[u] = x[u].x * c0 + x[u].y * c1 + x[u].z * c2 + x[u].w * c3;
#pragma unroll
    for (int u = 0; u < 8; u++) {
        v[u] += __shfl_xor_sync(0xffffffffu, v[u], 4);
        v[u] += __shfl_xor_sync(0xffffffffu, v[u], 2);
        v[u] += __shfl_xor_sync(0xffffffffu, v[u], 1);
    }
    if (g == 0) {
#pragma unroll
        for (int u = 0; u < 8; u++) sv[wid][u * 4 + sub] = v[u];
    }
    __syncwarp();

    // Full-width tail: lane l owns edge warp*32 + l
    int e = warp * 32 + lane;
    if (e < n_edges) {
        float val = sv[wid][lane];
        int s = src[e];
        int d = dst[e];
        g_t[e] = __ldg(&g_ssrc[s]) + val;
        g_rank[e] = atomicAdd(&g_deg[d], 1);
    }
}

// ---------------------------------------------------------------------------
// K3: SINGLE-LAUNCH exclusive scan of deg -> start.
// 196 blocks (co-resident) + device grid barrier.
// ---------------------------------------------------------------------------
__global__ __launch_bounds__(256) void k_scan(int n, int nb) {
    __shared__ int s[256];
    int t = threadIdx.x;
    int i = blockIdx.x * 256 + t;
    int v = (i < n) ? g_deg[i] : 0;
    s[t] = v;
    __syncthreads();
#pragma unroll
    for (int off = 1; off < 256; off <<= 1) {
        int x = (t >= off) ? s[t - off] : 0;
        __syncthreads();
        s[t] += x;
        __syncthreads();
    }
    int local_ex = s[t] - v;            // exclusive within block
    if (t == 255) g_blocksum[blockIdx.x] = s[255];

    // grid barrier
    __threadfence();
    __syncthreads();
    if (t == 0) {
        atomicAdd(&g_bar, 1);
        while (*((volatile int*)&g_bar) < nb) { }
    }
    __syncthreads();

    // phase 2: every block scans the blocksums (read L2-coherently)
    int bv = (t < nb) ? __ldcg(&g_blocksum[t]) : 0;
    s[t] = bv;
    __syncthreads();
#pragma unroll
    for (int off = 1; off < 256; off <<= 1) {
        int x = (t >= off) ? s[t - off] : 0;
        __syncthreads();
        s[t] += x;
        __syncthreads();
    }
    int offset = (blockIdx.x == 0) ? 0 : s[blockIdx.x - 1];
    if (i < n) g_start[i] = local_ex + offset;
}

// ---------------------------------------------------------------------------
// K4: per edge, NO atomics: pos = start[dst[e]] + rank[e]; pe[pos] = (src, t).
// 2 edges per thread; all reads coalesced except the hot start[] table.
// Also resets the scan barrier counter for the next replay.
// ---------------------------------------------------------------------------
__global__ __launch_bounds__(256) void k_edge_place(const int* __restrict__ src,
                                                    const int* __restrict__ dst,
                                                    int n_edges) {
    if (blockIdx.x == 0 && threadIdx.x == 0) g_bar = 0;  // reset for next replay
    int base = (blockIdx.x * blockDim.x + threadIdx.x) * 2;
    if (base >= n_edges) return;
    bool ok1 = (base + 1 < n_edges);

    int2 s2, d2, r2;
    float2 t2;
    if (ok1) {
        s2 = *reinterpret_cast<const int2*>(src + base);
        d2 = *reinterpret_cast<const int2*>(dst + base);
        r2 = *reinterpret_cast<const int2*>(g_rank + base);
        t2 = *reinterpret_cast<const float2*>(g_t + base);
    } else {
        s2.x = src[base]; d2.x = dst[base];
        r2.x = g_rank[base]; t2.x = g_t[base];
        s2.y = 0; d2.y = 0; r2.y = 0; t2.y = 0.f;
    }
    int pos0 = __ldg(&g_start[d2.x]) + r2.x;
    g_pe[pos0] = make_uint2((unsigned)s2.x, __float_as_uint(t2.x));
    if (ok1) {
        int pos1 = __ldg(&g_start[d2.y]) + r2.y;
        g_pe[pos1] = make_uint2((unsigned)s2.y, __float_as_uint(t2.y));
    }
}

// ---------------------------------------------------------------------------
// K5: HALF-WARP per dst node (16 lanes, uint4 gathers).
//     w_e = exp(leaky(t_e + sdst[d])); h[d] = (sum w_e*zh[src_e]) / sum w_e.
// ---------------------------------------------------------------------------
__global__ __launch_bounds__(256) void k_agg(float* __restrict__ out, int n_nodes) {
    int gw = (blockIdx.x * blockDim.x + threadIdx.x) >> 5;
    int lane = threadIdx.x & 31;
    int half = lane >> 4;
    int hl = lane & 15;
    int d = gw * 2 + half;
    if (d >= n_nodes) return;
    unsigned mask = half ? 0xFFFF0000u : 0x0000FFFFu;
    int lbase = half << 4;

    int start = g_start[d];
    int deg = g_deg[d];
    float sdst_d = g_sdst[d];
    float acc[8];
#pragma unroll
    for (int u = 0; u < 8; u++) acc[u] = 0.f;
    float wsum = 0.f;

    for (int i = 0; i < deg; i += 16) {
        int s = 0;
        float wv = 0.f;
        if (i + hl < deg) {
            uint2 p = g_pe[start + i + hl];
            s = (int)p.x;
            float ev = __uint_as_float(p.y) + sdst_d;
            ev = (ev > 0.f) ? ev : 0.01f * ev;
            wv = __expf(ev);
        }
        wsum += wv;
        int cnt = min(16, deg - i);
        int j = 0;
#define ACC_EDGE(hz, wj)                                                       \
        {                                                                      \
            float2 f0 = __half22float2(*reinterpret_cast<__half2*>(&hz.x));    \
            float2 f1 = __half22float2(*reinterpret_cast<__half2*>(&hz.y));    \
            float2 f2 = __half22float2(*reinterpret_cast<__half2*>(&hz.z));    \
            float2 f3 = __half22float2(*reinterpret_cast<__half2*>(&hz.w));    \
            acc[0] += (wj) * f0.x; acc[1] += (wj) * f0.y;                      \
            acc[2] += (wj) * f1.x; acc[3] += (wj) * f1.y;                      \
            acc[4] += (wj) * f2.x; acc[5] += (wj) * f2.y;                      \
            acc[6] += (wj) * f3.x; acc[7] += (wj) * f3.y;                      \
        }
        for (; j + 4 <= cnt; j += 4) {
            int s0 = __shfl_sync(mask, s, lbase + j);
            int s1 = __shfl_sync(mask, s, lbase + j + 1);
            int s2 = __shfl_sync(mask, s, lbase + j + 2);
            int s3 = __shfl_sync(mask, s, lbase + j + 3);
            float w0 = __shfl_sync(mask, wv, lbase + j);
            float w1 = __shfl_sync(mask, wv, lbase + j + 1);
            float w2 = __shfl_sync(mask, wv, lbase + j + 2);
            float w3 = __shfl_sync(mask, wv, lbase + j + 3);
            uint4 h0 = *reinterpret_cast<const uint4*>(g_zh + (size_t)s0 * 128 + hl * 8);
            uint4 h1 = *reinterpret_cast<const uint4*>(g_zh + (size_t)s1 * 128 + hl * 8);
            uint4 h2 = *reinterpret_cast<const uint4*>(g_zh + (size_t)s2 * 128 + hl * 8);
            uint4 h3 = *reinterpret_cast<const uint4*>(g_zh + (size_t)s3 * 128 + hl * 8);
            ACC_EDGE(h0, w0)
            ACC_EDGE(h1, w1)
            ACC_EDGE(h2, w2)
            ACC_EDGE(h3, w3)
        }
        for (; j < cnt; j++) {
            int sj = __shfl_sync(mask, s, lbase + j);
            float wj = __shfl_sync(mask, wv, lbase + j);
            uint4 hz = *reinterpret_cast<const uint4*>(g_zh + (size_t)sj * 128 + hl * 8);
            ACC_EDGE(hz, wj)
        }
#undef ACC_EDGE
    }
#pragma unroll
    for (int o = 1; o <= 8; o <<= 1)
        wsum += __shfl_xor_sync(mask, wsum, o);
    float dinv = (wsum > 0.f) ? 1.0f / wsum : 0.f;
    float4* op = (float4*)(out + (size_t)d * 128 + hl * 8);
    op[0] = make_float4(acc[0] * dinv, acc[1] * dinv, acc[2] * dinv, acc[3] * dinv);
    op[1] = make_float4(acc[4] * dinv, acc[5] * dinv, acc[6] * dinv, acc[7] * dinv);
}

// ---------------------------------------------------------------------------
extern "C" void kernel_launch(void* const* d_in, const int* in_sizes, int n_in,
                              void* d_out, int out_size) {
    const float* nf  = (const float*)d_in[0];
    const float* ef  = (const float*)d_in[1];
    const float* Wfc = (const float*)d_in[2];
    const float* Wa  = (const float*)d_in[3];
    const int*   src = (const int*)d_in[4];
    const int*   dst = (const int*)d_in[5];
    float* out = (float*)d_out;

    int n_nodes = in_sizes[0] / 128;
    int n_edges = in_sizes[4];
    int nscan = (n_nodes + 255) / 256;  // 196 (<= 256, co-resident)

    cudaFuncSetAttribute(k_gemm_h, cudaFuncAttributeMaxDynamicSharedMemorySize, GEMMH_SMEM);

    k_gemm_h<<<(n_nodes + 127) / 128, 256, GEMMH_SMEM>>>(nf, Wfc, Wa, n_nodes);
    k_se_hist<<<(n_edges + 255) / 256, 256>>>(ef, Wa, src, dst, n_edges);
    k_scan<<<nscan, 256>>>(n_nodes, nscan);
    k_edge_place<<<(n_edges + 511) / 512, 256>>>(src, dst, n_edges);
    k_agg<<<(n_nodes + 15) / 16, 256>>>(out, n_nodes);
}

// round 15
// speedup vs baseline: 1.0599x; 1.0332x over previous
#include <cuda_runtime.h>
#include <cuda_fp16.h>

#define NMAX_NODES 50000
#define NMAX_EDGES 800000

// Scratch (device globals; no allocation allowed)
__device__ __half g_zh[NMAX_NODES * 128];
__device__ float  g_ssrc[NMAX_NODES];
__device__ float  g_sdst[NMAX_NODES];
__device__ float  g_se[NMAX_EDGES];
__device__ int    g_rank[NMAX_EDGES];  // rank within dst segment (from histogram)
__device__ int    g_deg[NMAX_NODES];
__device__ int    g_start[NMAX_NODES];
__device__ int    g_blocksum[256];
__device__ int    g_bar;               // grid barrier counter (reset by k_edge_place)
__device__ uint2  g_pe[NMAX_EDGES];    // packed (src, t), dst-sorted

__device__ __forceinline__ unsigned smem_u32(const void* p) {
    unsigned a;
    asm("{ .reg .u64 t; cvta.to.shared.u64 t, %1; cvt.u32.u64 %0, t; }"
        : "=r"(a) : "l"(p));
    return a;
}

__device__ __forceinline__ void ldsm_x4(unsigned& r0, unsigned& r1, unsigned& r2,
                                        unsigned& r3, unsigned addr) {
    asm volatile("ldmatrix.sync.aligned.m8n8.x4.shared.b16 {%0,%1,%2,%3}, [%4];"
                 : "=r"(r0), "=r"(r1), "=r"(r2), "=r"(r3) : "r"(addr));
}
__device__ __forceinline__ void ldsm_x2(unsigned& r0, unsigned& r1, unsigned addr) {
    asm volatile("ldmatrix.sync.aligned.m8n8.x2.shared.b16 {%0,%1}, [%2];"
                 : "=r"(r0), "=r"(r1) : "r"(addr));
}
__device__ __forceinline__ void mma16816(float* c, const unsigned* a, const unsigned* b) {
    asm volatile(
        "mma.sync.aligned.m16n8k16.row.col.f32.f16.f16.f32 "
        "{%0,%1,%2,%3}, {%4,%5,%6,%7}, {%8,%9}, {%0,%1,%2,%3};"
        : "+f"(c[0]), "+f"(c[1]), "+f"(c[2]), "+f"(c[3])
        : "r"(a[0]), "r"(a[1]), "r"(a[2]), "r"(a[3]), "r"(b[0]), "r"(b[1]));
}

__device__ __forceinline__ unsigned pack_h2(float a, float b) {
    __half2 h = __floats2half2_rn(a, b);
    return *reinterpret_cast<unsigned*>(&h);
}

// ---------------------------------------------------------------------------
// K0 (stream B): zero deg
// ---------------------------------------------------------------------------
__global__ void k_zero(int n_nodes) {
    int i = blockIdx.x * blockDim.x + threadIdx.x;
    if (i < n_nodes) g_deg[i] = 0;
}

// ---------------------------------------------------------------------------
// K1 (main stream): z = nfeats @ W_fc^T via HMMA, fp32 converted inline.
// Fused epilogue: fp16 z + s_src/s_dst dots.
// ---------------------------------------------------------------------------
#define ASTR 136                 // padded row stride in halfs
#define GEMMH_SMEM (2 * 128 * ASTR * 2 + 288 * 4)

__global__ __launch_bounds__(256) void k_gemm_h(const float* __restrict__ nf,
                                                const float* __restrict__ W,
                                                const float* __restrict__ Wa,
                                                int n_nodes) {
    extern __shared__ __half hsm[];
    __half* sA = hsm;             // [128][ASTR]
    __half* sB = hsm + 128 * ASTR;
    float* sWa = reinterpret_cast<float*>(hsm + 2 * 128 * ASTR);  // [288]
    int tid = threadIdx.x;
    int rowBase = blockIdx.x * 128;

    if (tid < 144) {
        ((float2*)sWa)[tid] = ((const float2*)Wa)[tid];  // 288 floats
    }
#pragma unroll
    for (int c = tid; c < 2048; c += 256) {
        int row = c >> 4;
        int col16 = c & 15;                 // 8-half chunk
        int r = rowBase + row;
        uint4 hv = make_uint4(0u, 0u, 0u, 0u);
        if (r < n_nodes) {
            float4 v0 = ((const float4*)nf)[(size_t)r * 32 + col16 * 2];
            float4 v1 = ((const float4*)nf)[(size_t)r * 32 + col16 * 2 + 1];
            hv.x = pack_h2(v0.x, v0.y);
            hv.y = pack_h2(v0.z, v0.w);
            hv.z = pack_h2(v1.x, v1.y);
            hv.w = pack_h2(v1.z, v1.w);
        }
        *reinterpret_cast<uint4*>(sA + row * ASTR + col16 * 8) = hv;
        float4 w0 = ((const float4*)W)[row * 32 + col16 * 2];
        float4 w1 = ((const float4*)W)[row * 32 + col16 * 2 + 1];
        uint4 wv;
        wv.x = pack_h2(w0.x, w0.y);
        wv.y = pack_h2(w0.z, w0.w);
        wv.z = pack_h2(w1.x, w1.y);
        wv.w = pack_h2(w1.z, w1.w);
        *reinterpret_cast<uint4*>(sB + row * ASTR + col16 * 8) = wv;
    }
    __syncthreads();

    int warp = tid >> 5;
    int lane = tid & 31;
    int m0 = warp * 16;

    float acc[16][4];
#pragma unroll
    for (int nt = 0; nt < 16; nt++)
#pragma unroll
        for (int j = 0; j < 4; j++) acc[nt][j] = 0.f;

    unsigned aBase = smem_u32(sA) + ((m0 + (lane & 15)) * ASTR + ((lane >> 4) << 3)) * 2;
    unsigned bBase = smem_u32(sB) + ((lane & 7) * ASTR + (((lane >> 3) & 1) << 3)) * 2;

#pragma unroll
    for (int ks = 0; ks < 8; ks++) {
        unsigned a[4];
        ldsm_x4(a[0], a[1], a[2], a[3], aBase + ks * 32);
#pragma unroll
        for (int nt = 0; nt < 16; nt++) {
            unsigned b[2];
            ldsm_x2(b[0], b[1], bBase + (nt * 8 * ASTR) * 2 + ks * 32);
            mma16816(acc[nt], a, b);
        }
    }

    // Epilogue: z (fp16) + fused s_src/s_dst partial dots
    int gr = lane >> 2;
    int colq = (lane & 3) * 2;
    int r0 = rowBase + m0 + gr;
    int r1 = r0 + 8;
    float v1a = 0.f, v2a = 0.f, v1b = 0.f, v2b = 0.f;
#pragma unroll
    for (int nt = 0; nt < 16; nt++) {
        int col = nt * 8 + colq;
        float as0 = sWa[col], as1 = sWa[col + 1];
        float ad0 = sWa[160 + col], ad1 = sWa[161 + col];
        v1a += acc[nt][0] * as0 + acc[nt][1] * as1;
        v2a += acc[nt][0] * ad0 + acc[nt][1] * ad1;
        v1b += acc[nt][2] * as0 + acc[nt][3] * as1;
        v2b += acc[nt][2] * ad0 + acc[nt][3] * ad1;
        if (r0 < n_nodes) {
            unsigned h = pack_h2(acc[nt][0], acc[nt][1]);
            *reinterpret_cast<unsigned*>(g_zh + (size_t)r0 * 128 + col) = h;
        }
        if (r1 < n_nodes) {
            unsigned h = pack_h2(acc[nt][2], acc[nt][3]);
            *reinterpret_cast<unsigned*>(g_zh + (size_t)r1 * 128 + col) = h;
        }
    }
#pragma unroll
    for (int o = 1; o <= 2; o <<= 1) {
        v1a += __shfl_xor_sync(0xffffffffu, v1a, o);
        v2a += __shfl_xor_sync(0xffffffffu, v2a, o);
        v1b += __shfl_xor_sync(0xffffffffu, v1b, o);
        v2b += __shfl_xor_sync(0xffffffffu, v2b, o);
    }
    if ((lane & 3) == 0) {
        if (r0 < n_nodes) { g_ssrc[r0] = v1a; g_sdst[r0] = v2a; }
        if (r1 < n_nodes) { g_ssrc[r1] = v1b; g_sdst[r1] = v2b; }
    }
}

// ---------------------------------------------------------------------------
// K2 (stream B): coalesced s_e = efeats·a_e (MLP=8); full-width tail writes
// s_e and rank (histogram atomic return). No ssrc dependency -> overlaps gemm.
// ---------------------------------------------------------------------------
__global__ __launch_bounds__(256) void k_se_hist(const float* __restrict__ ef,
                                                 const float* __restrict__ Wa,
                                                 const int* __restrict__ dst,
                                                 int n_edges) {
    __shared__ float sa[32];
    __shared__ float sv[8][32];          // per-warp redistributed dots
    if (threadIdx.x < 32) sa[threadIdx.x] = Wa[128 + threadIdx.x];  // a_e
    __syncthreads();
    int wid = threadIdx.x >> 5;
    int warp = (blockIdx.x * blockDim.x + threadIdx.x) >> 5;
    int lane = threadIdx.x & 31;
    int sub = lane >> 3;
    int g = lane & 7;
    int e0 = warp * 32 + sub;

    float4 x[8];
#pragma unroll
    for (int u = 0; u < 8; u++) {
        int e = e0 + u * 4;
        x[u] = (e < n_edges) ? __ldg((const float4*)ef + (size_t)e * 8 + g)
                             : make_float4(0.f, 0.f, 0.f, 0.f);
    }
    float c0 = sa[g * 4], c1 = sa[g * 4 + 1], c2 = sa[g * 4 + 2], c3 = sa[g * 4 + 3];
    float v[8];
#pragma unroll
    for (int u = 0; u < 8; u++)
        v[u] = x[u].x * c0 + x[u].y * c1 + x[u].z * c2 + x[u].w * c3;
#pragma unroll
    for (int u = 0; u < 8; u++) {
        v[u] += __shfl_xor_sync(0xffffffffu, v[u], 4);
        v[u] += __shfl_xor_sync(0xffffffffu, v[u], 2);
        v[u] += __shfl_xor_sync(0xffffffffu, v[u], 1);
    }
    if (g == 0) {
#pragma unroll
        for (int u = 0; u < 8; u++) sv[wid][u * 4 + sub] = v[u];
    }
    __syncwarp();

    // Full-width tail: lane l owns edge warp*32 + l
    int e = warp * 32 + lane;
    if (e < n_edges) {
        g_se[e] = sv[wid][lane];
        g_rank[e] = atomicAdd(&g_deg[dst[e]], 1);
    }
}

// ---------------------------------------------------------------------------
// K3 (stream B): SINGLE-LAUNCH exclusive scan of deg -> start.
// 196 blocks (co-resident) + device grid barrier.
// ---------------------------------------------------------------------------
__global__ __launch_bounds__(256) void k_scan(int n, int nb) {
    __shared__ int s[256];
    int t = threadIdx.x;
    int i = blockIdx.x * 256 + t;
    int v = (i < n) ? g_deg[i] : 0;
    s[t] = v;
    __syncthreads();
#pragma unroll
    for (int off = 1; off < 256; off <<= 1) {
        int x = (t >= off) ? s[t - off] : 0;
        __syncthreads();
        s[t] += x;
        __syncthreads();
    }
    int local_ex = s[t] - v;            // exclusive within block
    if (t == 255) g_blocksum[blockIdx.x] = s[255];

    // grid barrier
    __threadfence();
    __syncthreads();
    if (t == 0) {
        atomicAdd(&g_bar, 1);
        while (*((volatile int*)&g_bar) < nb) { }
    }
    __syncthreads();

    // phase 2: every block scans the blocksums (read L2-coherently)
    int bv = (t < nb) ? __ldcg(&g_blocksum[t]) : 0;
    s[t] = bv;
    __syncthreads();
#pragma unroll
    for (int off = 1; off < 256; off <<= 1) {
        int x = (t >= off) ? s[t - off] : 0;
        __syncthreads();
        s[t] += x;
        __syncthreads();
    }
    int offset = (blockIdx.x == 0) ? 0 : s[blockIdx.x - 1];
    if (i < n) g_start[i] = local_ex + offset;
}

// ---------------------------------------------------------------------------
// K4 (after join): per edge, no atomics: t = ssrc[src]+se;
// pos = start[dst]+rank; pe[pos] = (src, t). 2 edges/thread.
// Also resets the scan barrier counter for the next replay.
// ---------------------------------------------------------------------------
__global__ __launch_bounds__(256) void k_edge_place(const int* __restrict__ src,
                                                    const int* __restrict__ dst,
                                                    int n_edges) {
    if (blockIdx.x == 0 && threadIdx.x == 0) g_bar = 0;  // reset for next replay
    int base = (blockIdx.x * blockDim.x + threadIdx.x) * 2;
    if (base >= n_edges) return;
    bool ok1 = (base + 1 < n_edges);

    int2 s2, d2, r2;
    float2 se2;
    if (ok1) {
        s2 = *reinterpret_cast<const int2*>(src + base);
        d2 = *reinterpret_cast<const int2*>(dst + base);
        r2 = *reinterpret_cast<const int2*>(g_rank + base);
        se2 = *reinterpret_cast<const float2*>(g_se + base);
    } else {
        s2.x = src[base]; d2.x = dst[base];
        r2.x = g_rank[base]; se2.x = g_se[base];
        s2.y = 0; d2.y = 0; r2.y = 0; se2.y = 0.f;
    }
    float t0 = __ldg(&g_ssrc[s2.x]) + se2.x;
    float t1 = ok1 ? (__ldg(&g_ssrc[s2.y]) + se2.y) : 0.f;
    int pos0 = __ldg(&g_start[d2.x]) + r2.x;
    g_pe[pos0] = make_uint2((unsigned)s2.x, __float_as_uint(t0));
    if (ok1) {
        int pos1 = __ldg(&g_start[d2.y]) + r2.y;
        g_pe[pos1] = make_uint2((unsigned)s2.y, __float_as_uint(t1));
    }
}

// ---------------------------------------------------------------------------
// K5: HALF-WARP per dst node (16 lanes, uint4 gathers).
//     w_e = exp(leaky(t_e + sdst[d])); h[d] = (sum w_e*zh[src_e]) / sum w_e.
// ---------------------------------------------------------------------------
__global__ __launch_bounds__(256) void k_agg(float* __restrict__ out, int n_nodes) {
    int gw = (blockIdx.x * blockDim.x + threadIdx.x) >> 5;
    int lane = threadIdx.x & 31;
    int half = lane >> 4;
    int hl = lane & 15;
    int d = gw * 2 + half;
    if (d >= n_nodes) return;
    unsigned mask = half ? 0xFFFF0000u : 0x0000FFFFu;
    int lbase = half << 4;

    int start = g_start[d];
    int deg = g_deg[d];
    float sdst_d = g_sdst[d];
    float acc[8];
#pragma unroll
    for (int u = 0; u < 8; u++) acc[u] = 0.f;
    float wsum = 0.f;

    for (int i = 0; i < deg; i += 16) {
        int s = 0;
        float wv = 0.f;
        if (i + hl < deg) {
            uint2 p = g_pe[start + i + hl];
            s = (int)p.x;
            float ev = __uint_as_float(p.y) + sdst_d;
            ev = (ev > 0.f) ? ev : 0.01f * ev;
            wv = __expf(ev);
        }
        wsum += wv;
        int cnt = min(16, deg - i);
        int j = 0;
#define ACC_EDGE(hz, wj)                                                       \
        {                                                                      \
            float2 f0 = __half22float2(*reinterpret_cast<__half2*>(&hz.x));    \
            float2 f1 = __half22float2(*reinterpret_cast<__half2*>(&hz.y));    \
            float2 f2 = __half22float2(*reinterpret_cast<__half2*>(&hz.z));    \
            float2 f3 = __half22float2(*reinterpret_cast<__half2*>(&hz.w));    \
            acc[0] += (wj) * f0.x; acc[1] += (wj) * f0.y;                      \
            acc[2] += (wj) * f1.x; acc[3] += (wj) * f1.y;                      \
            acc[4] += (wj) * f2.x; acc[5] += (wj) * f2.y;                      \
            acc[6] += (wj) * f3.x; acc[7] += (wj) * f3.y;                      \
        }
        for (; j + 4 <= cnt; j += 4) {
            int s0 = __shfl_sync(mask, s, lbase + j);
            int s1 = __shfl_sync(mask, s, lbase + j + 1);
            int s2 = __shfl_sync(mask, s, lbase + j + 2);
            int s3 = __shfl_sync(mask, s, lbase + j + 3);
            float w0 = __shfl_sync(mask, wv, lbase + j);
            float w1 = __shfl_sync(mask, wv, lbase + j + 1);
            float w2 = __shfl_sync(mask, wv, lbase + j + 2);
            float w3 = __shfl_sync(mask, wv, lbase + j + 3);
            uint4 h0 = *reinterpret_cast<const uint4*>(g_zh + (size_t)s0 * 128 + hl * 8);
            uint4 h1 = *reinterpret_cast<const uint4*>(g_zh + (size_t)s1 * 128 + hl * 8);
            uint4 h2 = *reinterpret_cast<const uint4*>(g_zh + (size_t)s2 * 128 + hl * 8);
            uint4 h3 = *reinterpret_cast<const uint4*>(g_zh + (size_t)s3 * 128 + hl * 8);
            ACC_EDGE(h0, w0)
            ACC_EDGE(h1, w1)
            ACC_EDGE(h2, w2)
            ACC_EDGE(h3, w3)
        }
        for (; j < cnt; j++) {
            int sj = __shfl_sync(mask, s, lbase + j);
            float wj = __shfl_sync(mask, wv, lbase + j);
            uint4 hz = *reinterpret_cast<const uint4*>(g_zh + (size_t)sj * 128 + hl * 8);
            ACC_EDGE(hz, wj)
        }
#undef ACC_EDGE
    }
#pragma unroll
    for (int o = 1; o <= 8; o <<= 1)
        wsum += __shfl_xor_sync(mask, wsum, o);
    float dinv = (wsum > 0.f) ? 1.0f / wsum : 0.f;
    float4* op = (float4*)(out + (size_t)d * 128 + hl * 8);
    op[0] = make_float4(acc[0] * dinv, acc[1] * dinv, acc[2] * dinv, acc[3] * dinv);
    op[1] = make_float4(acc[4] * dinv, acc[5] * dinv, acc[6] * dinv, acc[7] * dinv);
}

// ---------------------------------------------------------------------------
extern "C" void kernel_launch(void* const* d_in, const int* in_sizes, int n_in,
                              void* d_out, int out_size) {
    const float* nf  = (const float*)d_in[0];
    const float* ef  = (const float*)d_in[1];
    const float* Wfc = (const float*)d_in[2];
    const float* Wa  = (const float*)d_in[3];
    const int*   src = (const int*)d_in[4];
    const int*   dst = (const int*)d_in[5];
    float* out = (float*)d_out;

    int n_nodes = in_sizes[0] / 128;
    int n_edges = in_sizes[4];
    int nscan = (n_nodes + 255) / 256;  // 196 (<= 256, co-resident)

    // One-time host-side setup (no device memory involved).
    static cudaStream_t sB = nullptr;
    static cudaEvent_t evFork = nullptr, evJoin = nullptr;
    if (sB == nullptr) {
        cudaStreamCreateWithFlags(&sB, cudaStreamNonBlocking);
        cudaEventCreateWithFlags(&evFork, cudaEventDisableTiming);
        cudaEventCreateWithFlags(&evJoin, cudaEventDisableTiming);
        cudaFuncSetAttribute(k_gemm_h, cudaFuncAttributeMaxDynamicSharedMemorySize,
                             GEMMH_SMEM);
    }

    // Fork stream B off the main (capturing) stream.
    cudaEventRecord(evFork, 0);
    cudaStreamWaitEvent(sB, evFork, 0);

    // Edge pipeline (stream B): deg-zero -> edge dots + histogram/rank -> scan
    k_zero<<<(n_nodes + 255) / 256, 256, 0, sB>>>(n_nodes);
    k_se_hist<<<(n_edges + 255) / 256, 256, 0, sB>>>(ef, Wa, dst, n_edges);
    k_scan<<<nscan, 256, 0, sB>>>(n_nodes, nscan);
    cudaEventRecord(evJoin, sB);

    // Node pipeline (main stream): HMMA gemm + fused dots (overlaps stream B)
    k_gemm_h<<<(n_nodes + 127) / 128, 256, GEMMH_SMEM>>>(nf, Wfc, Wa, n_nodes);

    // Join, then the dependent tail on the main stream.
    cudaStreamWaitEvent(0, evJoin, 0);
    k_edge_place<<<(n_edges + 511) / 512, 256>>>(src, dst, n_edges);
    k_agg<<<(n_nodes + 15) / 16, 256>>>(out, n_nodes);
}